// round 17
// baseline (speedup 1.0000x reference)
#include <cuda_runtime.h>
#include <cuda_bf16.h>
#include <stdint.h>

#define NU 6041
#define NM 3953
#define B_TOTAL 1048576
#define NTILES 8192          // 128 rows per CTA-tile
#define GRID 740
#define THREADS 128          // 4 warps, 32 rows/warp
#define AW 28                // u32 words per A row (24 data + 4 pad)

typedef unsigned long long u64;
typedef unsigned int u32;
typedef unsigned short u16;

// ---- dynamic smem offsets (bytes) ----
#define OFF_A1    0u        // 4*32*28*4 = 14336
#define OFF_B1F   14336u    // 6144  (fp8 frags: 3kt * 4ntp * 32 * uint4)
#define OFF_B2F   20480u    // 4096  (bf16 frags: 4kt * 2ntp * 32 * uint4)
#define OFF_B3F   24576u    // 1024  (bf16 frags: 2kt * 2nt * 32 * uint2)
#define OFF_G     25600u    // 9216
#define OFF_WU    34816u    // 512
#define OFF_WM    35328u    // 512
#define OFF_B2B   35840u    // 128
#define OFF_B3B   35968u    // 64
#define OFF_W4    36032u    // 64
#define OFF_WR    36096u    // 96
#define OFF_SC    36192u    // 16
#define SMEM_BYTES 36224

__device__ uint4 gB1p[3 * 4 * 32];  // W1 fp8 B-fragments (row k=85 carries b1)
__device__ uint4 gB2p[4 * 2 * 32];  // W2 bf16 B-fragments
__device__ uint2 gB3[2 * 2 * 32];   // W3 bf16 B-fragments
__device__ u32   gU[NU * 16];       // per-user 64B row: 8 u32 e4m3 emb + wideW
__device__ u32   gM[NM * 16];       // per-movie row, same layout

// ---------------- helpers ----------------
__device__ __forceinline__ u32 pkbf(float lo, float hi) {
    u32 r; asm("cvt.rn.bf16x2.f32 %0,%1,%2;" : "=r"(r) : "f"(hi), "f"(lo)); return r;
}
__device__ __forceinline__ u32 maxbf2(u32 v) {
    u32 r; asm("max.bf16x2 %0,%1,%2;" : "=r"(r) : "r"(v), "r"(0u)); return r;
}
__device__ __forceinline__ u32 pk8x4(float f0, float f1, float f2, float f3) {
    u16 lo, hi;
    asm("cvt.rn.satfinite.e4m3x2.f32 %0,%1,%2;" : "=h"(lo) : "f"(f1), "f"(f0));
    asm("cvt.rn.satfinite.e4m3x2.f32 %0,%1,%2;" : "=h"(hi) : "f"(f3), "f"(f2));
    return (u32)lo | ((u32)hi << 16);
}
__device__ __forceinline__ u32 smem_u32(const void* p) {
    u32 a; asm("{ .reg .u64 t; cvta.to.shared.u64 t, %1; cvt.u32.u64 %0, t; }" : "=r"(a) : "l"(p));
    return a;
}
__device__ __forceinline__ void mma16816(float* c, const u32* a, u32 b0, u32 b1) {
    asm("mma.sync.aligned.m16n8k16.row.col.f32.bf16.bf16.f32 "
        "{%0,%1,%2,%3},{%4,%5,%6,%7},{%8,%9},{%0,%1,%2,%3};"
        : "+f"(c[0]), "+f"(c[1]), "+f"(c[2]), "+f"(c[3])
        : "r"(a[0]), "r"(a[1]), "r"(a[2]), "r"(a[3]), "r"(b0), "r"(b1));
}
__device__ __forceinline__ void mma16832(float* c, const u32* a, u32 b0, u32 b1) {
    asm("mma.sync.aligned.m16n8k32.row.col.f32.e4m3.e4m3.f32 "
        "{%0,%1,%2,%3},{%4,%5,%6,%7},{%8,%9},{%0,%1,%2,%3};"
        : "+f"(c[0]), "+f"(c[1]), "+f"(c[2]), "+f"(c[3])
        : "r"(a[0]), "r"(a[1]), "r"(a[2]), "r"(a[3]), "r"(b0), "r"(b1));
}
__device__ __forceinline__ void ldmA(u32* a, u32 saddr) {
    asm volatile("ldmatrix.sync.aligned.m8n8.x4.shared.b16 {%0,%1,%2,%3}, [%4];"
                 : "=r"(a[0]), "=r"(a[1]), "=r"(a[2]), "=r"(a[3]) : "r"(saddr));
}
__device__ __forceinline__ float relu(float x) { return fmaxf(x, 0.f); }

// ---------------- prep ----------------
__global__ void prep_kernel(const float* __restrict__ W1, const float* __restrict__ W2,
                            const float* __restrict__ W3,
                            const float* __restrict__ b1,
                            const float* __restrict__ utab, const float* __restrict__ mtab,
                            const float* __restrict__ wideW) {
    int i = blockIdx.x * blockDim.x + threadIdx.x;
    int stride = gridDim.x * blockDim.x;

    // W1 fp8 packed fragments; row k=85 carries b1 (A provides const 1.0 there)
    for (int idx = i; idx < 3 * 4 * 32; idx += stride) {
        int lane = idx & 31, ntp = (idx >> 5) & 3, kt = idx >> 7;
        int g = lane >> 2, t = lane & 3;
        int n0 = ntp * 16 + g, n1 = n0 + 8;
        int kb = kt * 32 + 4 * t;
        float v[8];
        #pragma unroll
        for (int j = 0; j < 4; j++) {
            int ka = kb + j, kc = kb + 16 + j;
            v[j]     = (ka < 85) ? W1[ka * 64 + n0] : ((ka == 85) ? b1[n0] : 0.f);
            v[4 + j] = (kc < 85) ? W1[kc * 64 + n0] : ((kc == 85) ? b1[n0] : 0.f);
        }
        u32 b0n0 = pk8x4(v[0], v[1], v[2], v[3]);
        u32 b1n0 = pk8x4(v[4], v[5], v[6], v[7]);
        #pragma unroll
        for (int j = 0; j < 4; j++) {
            int ka = kb + j, kc = kb + 16 + j;
            v[j]     = (ka < 85) ? W1[ka * 64 + n1] : ((ka == 85) ? b1[n1] : 0.f);
            v[4 + j] = (kc < 85) ? W1[kc * 64 + n1] : ((kc == 85) ? b1[n1] : 0.f);
        }
        gB1p[idx] = make_uint4(b0n0, b1n0, pk8x4(v[0], v[1], v[2], v[3]),
                               pk8x4(v[4], v[5], v[6], v[7]));
    }
    // W2 bf16 packed fragments
    for (int idx = i; idx < 4 * 2 * 32; idx += stride) {
        int lane = idx & 31, ntp = (idx >> 5) & 1, kt = idx >> 6;
        int g = lane >> 2, t = lane & 3;
        int n0 = ntp * 16 + g, n1 = n0 + 8;
        int k0 = kt * 16 + t * 2;
        gB2p[idx] = make_uint4(
            pkbf(W2[k0 * 32 + n0],       W2[(k0 + 1) * 32 + n0]),
            pkbf(W2[(k0 + 8) * 32 + n0], W2[(k0 + 9) * 32 + n0]),
            pkbf(W2[k0 * 32 + n1],       W2[(k0 + 1) * 32 + n1]),
            pkbf(W2[(k0 + 8) * 32 + n1], W2[(k0 + 9) * 32 + n1]));
    }
    // W3 bf16 fragments
    for (int idx = i; idx < 2 * 2 * 32; idx += stride) {
        int lane = idx & 31, nt = (idx >> 5) & 1, kt = idx >> 6;
        int g = lane >> 2, t = lane & 3;
        int n = nt * 8 + g;
        int k0 = kt * 16 + t * 2;
        gB3[idx] = make_uint2(pkbf(W3[k0 * 16 + n],       W3[(k0 + 1) * 16 + n]),
                              pkbf(W3[(k0 + 8) * 16 + n], W3[(k0 + 9) * 16 + n]));
    }
    // fp8 gather tables
    for (int idx = i; idx < NU * 2; idx += stride) {
        int id = idx >> 1, j = idx & 1;
        const float* e = utab + id * 32 + j * 16;
        ((uint4*)(gU + id * 16))[j] = make_uint4(
            pk8x4(e[0], e[1], e[2], e[3]),   pk8x4(e[4], e[5], e[6], e[7]),
            pk8x4(e[8], e[9], e[10], e[11]), pk8x4(e[12], e[13], e[14], e[15]));
    }
    for (int idx = i; idx < NM * 2; idx += stride) {
        int id = idx >> 1, j = idx & 1;
        const float* e = mtab + id * 32 + j * 16;
        ((uint4*)(gM + id * 16))[j] = make_uint4(
            pk8x4(e[0], e[1], e[2], e[3]),   pk8x4(e[4], e[5], e[6], e[7]),
            pk8x4(e[8], e[9], e[10], e[11]), pk8x4(e[12], e[13], e[14], e[15]));
    }
    for (int id = i; id < NU; id += stride) gU[id * 16 + 8] = __float_as_uint(wideW[id]);
    for (int id = i; id < NM; id += stride) gM[id * 16 + 8] = __float_as_uint(wideW[NU + id]);
}

// ---------------- main kernel ----------------
__global__ void __launch_bounds__(THREADS, 5)
wd_mma(const int* __restrict__ uids, const int* __restrict__ mids,
       const float* __restrict__ gender, const float* __restrict__ age,
       const float* __restrict__ occ, const float* __restrict__ genres,
       const float* __restrict__ wideW, const float* __restrict__ wideB,
       const float* __restrict__ b2, const float* __restrict__ b3,
       const float* __restrict__ W4, const float* __restrict__ b4,
       float* __restrict__ out)
{
    extern __shared__ __align__(16) char smem[];
    u32*   sA1w  = (u32*)(smem + OFF_A1);
    uint4* sB1p  = (uint4*)(smem + OFF_B1F);
    uint4* sB2p  = (uint4*)(smem + OFF_B2F);
    uint2* sB3f  = (uint2*)(smem + OFF_B3F);
    float* sG    = (float*)(smem + OFF_G);
    float* sWU   = (float*)(smem + OFF_WU);
    float* sWM   = (float*)(smem + OFF_WM);
    float* sB2b  = (float*)(smem + OFF_B2B);
    float* sB3b  = (float*)(smem + OFF_B3B);
    float* sW4   = (float*)(smem + OFF_W4);
    float* sWr   = (float*)(smem + OFF_WR);
    float* sSc   = (float*)(smem + OFF_SC);

    const int tid  = threadIdx.x;
    const int wid  = tid >> 5;
    const int lane = tid & 31;
    const int g    = lane >> 2;
    const int t4   = lane & 3;
    const int c0   = 2 * t4;

    // ---- one-time staging ----
    for (int i = tid; i < 3 * 4 * 32; i += THREADS) sB1p[i] = gB1p[i];
    for (int i = tid; i < 4 * 2 * 32; i += THREADS) sB2p[i] = gB2p[i];
    if (tid < 2 * 2 * 32) sB3f[tid] = gB3[tid];
    if (tid < 32) sB2b[tid] = b2[tid];
    if (tid < 16) sB3b[tid] = b3[tid];
    if (tid < 16) sW4[tid]  = W4[tid];
    if (tid < 21) sWr[tid]  = wideW[NU + NM + tid];
    if (tid == 0) { sSc[0] = b4[0]; sSc[1] = wideB[0]; }
    __syncthreads();

    u32*   myA   = sA1w + wid * (32 * AW);
    float* myG   = sG + wid * 576;
    float* myWU  = sWU + wid * 32;
    float* myWM  = sWM + wid * 32;

    const u32 aBase = smem_u32(myA);
    const u32 aAddr = aBase + (u32)(((lane & 15) * AW + (lane >> 4) * 4) * 4);

    // ---- prefetch first tile's ids ----
    int pu = 0, pm = 0;
    if (blockIdx.x < NTILES) {
        pu = uids[blockIdx.x * 128 + wid * 32 + lane];
        pm = mids[blockIdx.x * 128 + wid * 32 + lane];
    }

    const int ch  = lane & 1;     // 16B chunk within 32B emb row
    const int r16 = lane >> 1;    // row index 0..15

    for (int tile = blockIdx.x; tile < NTILES; tile += gridDim.x) {
        const int R = tile * 128 + wid * 32;
        __syncwarp();   // prior iteration's ldmA reads done before new stores

        // ---- gather ids via shfl, issue big LDGs FIRST ----
        const int u0 = __shfl_sync(0xffffffffu, pu, r16);
        const int m0 = __shfl_sync(0xffffffffu, pm, r16);
        const int u1 = __shfl_sync(0xffffffffu, pu, r16 + 16);
        const int m1 = __shfl_sync(0xffffffffu, pm, r16 + 16);
        const u32* ub0 = gU + (u32)u0 * 16;
        const u32* mb0 = gM + (u32)m0 * 16;
        const u32* ub1 = gU + (u32)u1 * 16;
        const u32* mb1 = gM + (u32)m1 * 16;
        uint4 vu0 = ((const uint4*)ub0)[ch];
        uint4 vm0 = ((const uint4*)mb0)[ch];
        uint4 vu1 = ((const uint4*)ub1)[ch];
        uint4 vm1 = ((const uint4*)mb1)[ch];
        float wu0 = 0.f, wm0 = 0.f, wu1 = 0.f, wm1 = 0.f;
        if (ch == 0) {
            wu0 = __uint_as_float(ub0[8]); wm0 = __uint_as_float(mb0[8]);
            wu1 = __uint_as_float(ub1[8]); wm1 = __uint_as_float(mb1[8]);
        }

        // ---- genres (coalesced stream) ----
        float2 gg[9];
        {
            const float2* gb = (const float2*)(genres + (size_t)R * 18);
            #pragma unroll
            for (int j = 0; j < 9; j++) gg[j] = gb[lane + 32 * j];
        }

        // ---- stores: gather rows + wide scalars + genres ----
        {
            u32* rb0 = myA + r16 * AW;
            u32* rb1 = myA + (r16 + 16) * AW;
            *(uint4*)(rb0 + 4 * ch)     = vu0;
            *(uint4*)(rb0 + 8 + 4 * ch) = vm0;
            *(uint4*)(rb1 + 4 * ch)     = vu1;
            *(uint4*)(rb1 + 8 + 4 * ch) = vm1;
            if (ch == 0) {
                myWU[r16] = wu0;      myWM[r16] = wm0;
                myWU[r16 + 16] = wu1; myWM[r16 + 16] = wm1;
            }
            float2* mg = (float2*)myG;
            #pragma unroll
            for (int j = 0; j < 9; j++) mg[lane + 32 * j] = gg[j];
        }
        __syncwarp();

        // ---- rest features (fp8, const-1 at k=85) + wide path ----
        float wide;
        {
            float fv[21];
            fv[0] = gender[R + lane]; fv[1] = age[R + lane]; fv[2] = occ[R + lane];
            #pragma unroll
            for (int q = 0; q < 9; q++) {
                float2 p = *(const float2*)(myG + lane * 18 + 2 * q);
                fv[3 + 2 * q] = p.x; fv[4 + 2 * q] = p.y;
            }
            float wa = sSc[1] + myWU[lane] + myWM[lane];
            float wb = 0.f, wc = 0.f;
            #pragma unroll
            for (int i = 0; i < 7; i++) {
                wa = fmaf(fv[3 * i],     sWr[3 * i],     wa);
                wb = fmaf(fv[3 * i + 1], sWr[3 * i + 1], wb);
                wc = fmaf(fv[3 * i + 2], sWr[3 * i + 2], wc);
            }
            wide = wa + wb + wc;

            u32 w[8];
            w[0] = pk8x4(fv[0],  fv[1],  fv[2],  fv[3]);
            w[1] = pk8x4(fv[4],  fv[5],  fv[6],  fv[7]);
            w[2] = pk8x4(fv[8],  fv[9],  fv[10], fv[11]);
            w[3] = pk8x4(fv[12], fv[13], fv[14], fv[15]);
            w[4] = pk8x4(fv[16], fv[17], fv[18], fv[19]);
            w[5] = pk8x4(fv[20], 1.0f, 0.f, 0.f);   // k=85 const 1.0 -> b1 row
            w[6] = 0u; w[7] = 0u;
            u32* rb = myA + lane * AW + 16;
            *(uint4*)(rb)     = make_uint4(w[0], w[1], w[2], w[3]);
            *(uint4*)(rb + 4) = make_uint4(w[4], w[5], w[6], w[7]);
        }
        __syncwarp();

        // ---- prefetch NEXT tile's ids (hidden under MMA section) ----
        {
            int nt2 = tile + gridDim.x;
            if (nt2 < NTILES) {
                pu = uids[nt2 * 128 + wid * 32 + lane];
                pm = mids[nt2 * 128 + wid * 32 + lane];
            }
        }

        // ---- layer 1 (fp8, k=96), N-split into two halves to cap reg pressure ----
        u32 a2f[2][4][4];
        #pragma unroll
        for (int half = 0; half < 2; half++) {
            float acc[2][4][4];
            #pragma unroll
            for (int m = 0; m < 2; m++)
                #pragma unroll
                for (int nt = 0; nt < 4; nt++)
                    acc[m][nt][0] = acc[m][nt][1] = acc[m][nt][2] = acc[m][nt][3] = 0.f;
            #pragma unroll
            for (int kt = 0; kt < 3; kt++) {
                u32 a0[4], a1[4];
                ldmA(a0, aAddr + kt * 32u);
                ldmA(a1, aAddr + 16u * AW * 4u + kt * 32u);
                #pragma unroll
                for (int ntp = 0; ntp < 2; ntp++) {
                    uint4 q = sB1p[(kt * 4 + half * 2 + ntp) * 32 + lane];
                    mma16832(acc[0][2*ntp],     a0, q.x, q.y);
                    mma16832(acc[0][2*ntp + 1], a0, q.z, q.w);
                    mma16832(acc[1][2*ntp],     a1, q.x, q.y);
                    mma16832(acc[1][2*ntp + 1], a1, q.z, q.w);
                }
            }
            // epilogue 1 for this half: pack + packed-relu -> a2f k-tiles 2h, 2h+1
            #pragma unroll
            for (int m = 0; m < 2; m++)
                #pragma unroll
                for (int p = 0; p < 2; p++) {
                    int j0 = 2 * p, j1 = j0 + 1;
                    a2f[m][half * 2 + p][0] = maxbf2(pkbf(acc[m][j0][0], acc[m][j0][1]));
                    a2f[m][half * 2 + p][1] = maxbf2(pkbf(acc[m][j0][2], acc[m][j0][3]));
                    a2f[m][half * 2 + p][2] = maxbf2(pkbf(acc[m][j1][0], acc[m][j1][1]));
                    a2f[m][half * 2 + p][3] = maxbf2(pkbf(acc[m][j1][2], acc[m][j1][3]));
                }
        }

        // ---- layer 2 (bf16, k=64; bias init from smem) ----
        float acc2[2][4][4];
        #pragma unroll
        for (int nt = 0; nt < 4; nt++) {
            float2 bb = *(const float2*)(sB2b + nt * 8 + c0);
            #pragma unroll
            for (int m = 0; m < 2; m++) {
                acc2[m][nt][0] = bb.x; acc2[m][nt][1] = bb.y;
                acc2[m][nt][2] = bb.x; acc2[m][nt][3] = bb.y;
            }
        }
        #pragma unroll
        for (int kt = 0; kt < 4; kt++)
            #pragma unroll
            for (int ntp = 0; ntp < 2; ntp++) {
                uint4 q = sB2p[(kt * 2 + ntp) * 32 + lane];
                mma16816(acc2[0][2*ntp],     a2f[0][kt], q.x, q.y);
                mma16816(acc2[0][2*ntp + 1], a2f[0][kt], q.z, q.w);
                mma16816(acc2[1][2*ntp],     a2f[1][kt], q.x, q.y);
                mma16816(acc2[1][2*ntp + 1], a2f[1][kt], q.z, q.w);
            }

        // ---- epilogue 2 + layer 3 (k=32; bias init + B-frags from smem) + tail ----
        #pragma unroll
        for (int m = 0; m < 2; m++) {
            u32 a3f[2][4];
            #pragma unroll
            for (int kt = 0; kt < 2; kt++) {
                int j0 = 2 * kt, j1 = j0 + 1;
                a3f[kt][0] = maxbf2(pkbf(acc2[m][j0][0], acc2[m][j0][1]));
                a3f[kt][1] = maxbf2(pkbf(acc2[m][j0][2], acc2[m][j0][3]));
                a3f[kt][2] = maxbf2(pkbf(acc2[m][j1][0], acc2[m][j1][1]));
                a3f[kt][3] = maxbf2(pkbf(acc2[m][j1][2], acc2[m][j1][3]));
            }
            float acc3[2][4];
            {
                float2 bb0 = *(const float2*)(sB3b + c0);
                float2 bb1 = *(const float2*)(sB3b + 8 + c0);
                acc3[0][0] = bb0.x; acc3[0][1] = bb0.y; acc3[0][2] = bb0.x; acc3[0][3] = bb0.y;
                acc3[1][0] = bb1.x; acc3[1][1] = bb1.y; acc3[1][2] = bb1.x; acc3[1][3] = bb1.y;
            }
            #pragma unroll
            for (int kt = 0; kt < 2; kt++)
                #pragma unroll
                for (int nt = 0; nt < 2; nt++) {
                    uint2 q = sB3f[(kt * 2 + nt) * 32 + lane];
                    mma16816(acc3[nt], a3f[kt], q.x, q.y);
                }

            float2 w4a = *(const float2*)(sW4 + c0);
            float2 w4b = *(const float2*)(sW4 + 8 + c0);
            float dpg, dph;
            dpg  = relu(acc3[0][0]) * w4a.x;
            dpg  = fmaf(relu(acc3[0][1]), w4a.y, dpg);
            dpg  = fmaf(relu(acc3[1][0]), w4b.x, dpg);
            dpg  = fmaf(relu(acc3[1][1]), w4b.y, dpg);
            dph  = relu(acc3[0][2]) * w4a.x;
            dph  = fmaf(relu(acc3[0][3]), w4a.y, dph);
            dph  = fmaf(relu(acc3[1][2]), w4b.x, dph);
            dph  = fmaf(relu(acc3[1][3]), w4b.y, dph);
            dpg += __shfl_xor_sync(0xffffffffu, dpg, 1);
            dpg += __shfl_xor_sync(0xffffffffu, dpg, 2);
            dph += __shfl_xor_sync(0xffffffffu, dph, 1);
            dph += __shfl_xor_sync(0xffffffffu, dph, 2);

            float wg = __shfl_sync(0xffffffffu, wide, m * 16 + g);
            float wh = __shfl_sync(0xffffffffu, wide, m * 16 + 8 + g);
            if (t4 == 0) {
                float zg = wg + dpg + sSc[0];
                float zh = wh + dph + sSc[0];
                out[R + m * 16 + g]     = __fdividef(1.f, 1.f + __expf(-zg));
                out[R + m * 16 + 8 + g] = __fdividef(1.f, 1.f + __expf(-zh));
            }
        }
    }
}

extern "C" void kernel_launch(void* const* d_in, const int* in_sizes, int n_in,
                              void* d_out, int out_size) {
    const int*   uids   = (const int*)  d_in[0];
    const int*   mids   = (const int*)  d_in[1];
    const float* gender = (const float*)d_in[2];
    const float* age    = (const float*)d_in[3];
    const float* occ    = (const float*)d_in[4];
    const float* genres = (const float*)d_in[5];
    const float* wideW  = (const float*)d_in[6];
    const float* wideB  = (const float*)d_in[7];
    const float* utab   = (const float*)d_in[8];
    const float* mtab   = (const float*)d_in[9];
    const float* W1     = (const float*)d_in[10];
    const float* b1     = (const float*)d_in[11];
    const float* W2     = (const float*)d_in[12];
    const float* b2     = (const float*)d_in[13];
    const float* W3     = (const float*)d_in[14];
    const float* b3     = (const float*)d_in[15];
    const float* W4     = (const float*)d_in[16];
    const float* b4     = (const float*)d_in[17];
    float* out = (float*)d_out;

    static int inited = 0;
    if (!inited) {
        cudaFuncSetAttribute(wd_mma, cudaFuncAttributeMaxDynamicSharedMemorySize, SMEM_BYTES);
        inited = 1;
    }

    prep_kernel<<<148, 256>>>(W1, W2, W3, b1, utab, mtab, wideW);
    wd_mma<<<GRID, THREADS, SMEM_BYTES>>>(uids, mids, gender, age, occ, genres,
                                          wideW, wideB, b2, b3, W4, b4, out);
}